// round 9
// baseline (speedup 1.0000x reference)
#include <cuda_runtime.h>
#include <cuda_bf16.h>
#include <cstdint>
#include <cmath>

// loss = mean((normalize(E) @ normalize(E)^T - S)^2), E:[N,128] f32, S:[N,N] f32, N=8192.
//
// v8: v3 (best structure) + persistent G=148 (1 CTA/SM, matches measured occ)
//     with tight one-tile-ahead S prefetch -> continuous DRAM stream.
//  - Upper-triangular 128x128 pred tiles; each scored vs S[i,j] AND S[j,i].
//  - Loss is register-direct (v3 style, proven); next-tile A/B cp.async is
//    issued AFTER the loss LDGs so they don't queue behind it in L1tex.
//  - prefetch(t+1) right after MMA(t): <=1.2 tiles of prefetched lines in L2
//    (~24MB at G=148) -> no v5-style thrash.
//  - Deterministic: per-tile partials + fixed-order finalize.

#define DK 128
#define MAX_N 8192
#define MAX_T (MAX_N / 128)
#define LDA 136                          // bf16 smem row stride (ldmatrix-safe)

#define SZ_AB (128 * LDA * 2)            // 34816 B per tile
#define SMEM_BYTES (2 * SZ_AB)           // 69632 B

__device__ __nv_bfloat16 g_xn[(size_t)MAX_N * DK];
__device__ float g_partials[MAX_T * (MAX_T + 1) / 2];

// ---------------------------------------------------------------------------
__global__ void __launch_bounds__(512) normalize_kernel(const float* __restrict__ emb, int N) {
    int wid = threadIdx.x >> 5, lane = threadIdx.x & 31;
    int row = blockIdx.x * 16 + wid;
    if (row >= N) return;
    float4 v = reinterpret_cast<const float4*>(emb + (size_t)row * DK)[lane];
    float ss = v.x * v.x + v.y * v.y + v.z * v.z + v.w * v.w;
#pragma unroll
    for (int o = 16; o; o >>= 1) ss += __shfl_xor_sync(0xffffffffu, ss, o);
    float inv = 1.0f / fmaxf(sqrtf(ss), 1e-8f);
    __nv_bfloat16* dst = g_xn + (size_t)row * DK + lane * 4;
    dst[0] = __float2bfloat16(v.x * inv);
    dst[1] = __float2bfloat16(v.y * inv);
    dst[2] = __float2bfloat16(v.z * inv);
    dst[3] = __float2bfloat16(v.w * inv);
}

// ---------------------------------------------------------------------------
__device__ __forceinline__ void cp_async16(void* smem_dst, const void* gmem_src) {
    uint32_t d = (uint32_t)__cvta_generic_to_shared(smem_dst);
    asm volatile("cp.async.cg.shared.global [%0], [%1], 16;" :: "r"(d), "l"(gmem_src));
}
__device__ __forceinline__ void l2_prefetch(const void* g) {
    asm volatile("prefetch.global.L2 [%0];" :: "l"(g));
}
__device__ __forceinline__ void ldsm_x4(uint32_t& r0, uint32_t& r1, uint32_t& r2, uint32_t& r3,
                                        const void* p) {
    uint32_t addr = (uint32_t)__cvta_generic_to_shared(p);
    asm volatile("ldmatrix.sync.aligned.m8n8.x4.shared.b16 {%0,%1,%2,%3}, [%4];"
                 : "=r"(r0), "=r"(r1), "=r"(r2), "=r"(r3) : "r"(addr));
}
__device__ __forceinline__ void mma_bf16(float* c, const uint32_t* a, uint32_t b0, uint32_t b1) {
    asm volatile(
        "mma.sync.aligned.m16n8k16.row.col.f32.bf16.bf16.f32 "
        "{%0,%1,%2,%3}, {%4,%5,%6,%7}, {%8,%9}, {%0,%1,%2,%3};"
        : "+f"(c[0]), "+f"(c[1]), "+f"(c[2]), "+f"(c[3])
        : "r"(a[0]), "r"(a[1]), "r"(a[2]), "r"(a[3]), "r"(b0), "r"(b1));
}
__device__ __forceinline__ void decode_tile(int idx, int T, int& bi, int& bj) {
    int b = 0;
    while (idx >= T - b) { idx -= T - b; b++; }
    bi = b; bj = b + idx;
}

// ---------------------------------------------------------------------------
__global__ void __launch_bounds__(512) gemm_loss_kernel(const float* __restrict__ S,
                                                        int N, int T, int ntiles) {
    extern __shared__ char smem[];
    __nv_bfloat16* sA = (__nv_bfloat16*)smem;
    __nv_bfloat16* sB = (__nv_bfloat16*)(smem + SZ_AB);
    __shared__ float rbuf[16];

    const int t = threadIdx.x;
    const int G = gridDim.x;
    const int w = t >> 5, lane = t & 31;
    const int wm = w & 3, wn = w >> 2;
    const int g = lane >> 2, t4 = lane & 3;

    const int a_row_in16 = lane & 15;
    const int a_khalf = (lane >> 4) * 8;
    const int b_row_in16 = (lane & 7) + ((lane >> 4) << 3);
    const int b_khalf = ((lane >> 3) & 1) * 8;

    const int pf_r = t >> 2, pf_q = (t & 3) * 32;   // 1 line / thread / S block

    int tile = blockIdx.x;
    if (tile >= ntiles) return;
    int bi, bj;
    decode_tile(tile, T, bi, bj);

    // ---- prologue: A/B(t0) + S(t0) prefetch ----
    {
        int i0 = bi * 128, j0 = bj * 128;
#pragma unroll
        for (int it = 0; it < 4; it++) {
            int id = t + it * 512;
            int r = id >> 4, q = id & 15;
            cp_async16(sA + r * LDA + q * 8, g_xn + (size_t)(i0 + r) * DK + q * 8);
            cp_async16(sB + r * LDA + q * 8, g_xn + (size_t)(j0 + r) * DK + q * 8);
        }
        asm volatile("cp.async.commit_group;");
        l2_prefetch(S + (size_t)(i0 + pf_r) * N + j0 + pf_q);
        if (bi != bj) l2_prefetch(S + (size_t)(j0 + pf_r) * N + i0 + pf_q);
    }

#pragma unroll 1
    for (; tile < ntiles; tile += G) {
        const int i0 = bi * 128, j0 = bj * 128;
        const bool offdiag = (bi != bj);

        const int nt = tile + G;
        int nbi = bi, nbj = bj;
        if (nt < ntiles) decode_tile(nt, T, nbi, nbj);
        const int ni0 = nbi * 128, nj0 = nbj * 128;

        // ---- wait A/B(t) ----
        asm volatile("cp.async.wait_group 0;" ::: "memory");
        __syncthreads();

        // ---- GEMM: 16 warps x (32x32) ----
        float acc[2][4][4];
#pragma unroll
        for (int mi = 0; mi < 2; mi++)
#pragma unroll
            for (int ni = 0; ni < 4; ni++)
#pragma unroll
                for (int e = 0; e < 4; e++) acc[mi][ni][e] = 0.0f;

#pragma unroll
        for (int k0 = 0; k0 < DK; k0 += 16) {
            uint32_t a[2][4], b[2][4];
#pragma unroll
            for (int mi = 0; mi < 2; mi++) {
                const __nv_bfloat16* p =
                    sA + (wm * 32 + mi * 16 + a_row_in16) * LDA + (k0 + a_khalf);
                ldsm_x4(a[mi][0], a[mi][1], a[mi][2], a[mi][3], p);
            }
#pragma unroll
            for (int nj = 0; nj < 2; nj++) {
                const __nv_bfloat16* p =
                    sB + (wn * 32 + nj * 16 + b_row_in16) * LDA + (k0 + b_khalf);
                ldsm_x4(b[nj][0], b[nj][1], b[nj][2], b[nj][3], p);
            }
#pragma unroll
            for (int mi = 0; mi < 2; mi++)
#pragma unroll
                for (int ni = 0; ni < 4; ni++) {
                    const uint32_t* bp = &b[ni >> 1][(ni & 1) * 2];
                    mma_bf16(acc[mi][ni], a[mi], bp[0], bp[1]);
                }
        }
        __syncthreads();     // sA/sB dead; safe for next-tile cp.async below

        // ---- start NEXT tile's S stream now (overlaps loss below) ----
        if (nt < ntiles) {
            l2_prefetch(S + (size_t)(ni0 + pf_r) * N + nj0 + pf_q);
            if (nbi != nbj) l2_prefetch(S + (size_t)(nj0 + pf_r) * N + ni0 + pf_q);
        }

        // ---- loss: register-direct (v3, proven) ----
        float lsum = 0.0f;
#pragma unroll
        for (int mi = 0; mi < 2; mi++)
#pragma unroll
            for (int e2 = 0; e2 < 2; e2++) {
                const float* rowp = S + (size_t)(i0 + wm * 32 + mi * 16 + g + e2 * 8) * N + j0
                                    + wn * 32 + t4 * 2;
#pragma unroll
                for (int ni = 0; ni < 4; ni++) {
                    float2 s = *reinterpret_cast<const float2*>(rowp + ni * 8);
                    float d0 = acc[mi][ni][e2 * 2 + 0] - s.x;
                    float d1 = acc[mi][ni][e2 * 2 + 1] - s.y;
                    lsum += d0 * d0 + d1 * d1;
                }
            }
        if (offdiag) {
#pragma unroll
            for (int ni = 0; ni < 4; ni++)
#pragma unroll
                for (int e1 = 0; e1 < 2; e1++) {
                    const float* colp = S + (size_t)(j0 + wn * 32 + ni * 8 + t4 * 2 + e1) * N
                                        + i0 + wm * 32 + g;
#pragma unroll
                    for (int mi = 0; mi < 2; mi++)
#pragma unroll
                        for (int e2 = 0; e2 < 2; e2++) {
                            float d = acc[mi][ni][e2 * 2 + e1] - colp[mi * 16 + e2 * 8];
                            lsum += d * d;
                        }
                }
        }

        // ---- next tile's A/B cp.async (after loss LDGs: stays behind them) ----
        if (nt < ntiles) {
#pragma unroll
            for (int it = 0; it < 4; it++) {
                int id = t + it * 512;
                int r = id >> 4, q = id & 15;
                cp_async16(sA + r * LDA + q * 8, g_xn + (size_t)(ni0 + r) * DK + q * 8);
                cp_async16(sB + r * LDA + q * 8, g_xn + (size_t)(nj0 + r) * DK + q * 8);
            }
            asm volatile("cp.async.commit_group;");
        }

        // ---- deterministic reduction -> per-tile partial ----
#pragma unroll
        for (int o = 16; o; o >>= 1) lsum += __shfl_xor_sync(0xffffffffu, lsum, o);
        if (lane == 0) rbuf[w] = lsum;
        __syncthreads();
        if (t == 0) {
            float s = 0.0f;
#pragma unroll
            for (int i = 0; i < 16; i++) s += rbuf[i];
            g_partials[tile] = s;
        }
        __syncthreads();     // rbuf reuse safety

        bi = nbi; bj = nbj;
    }
}

// ---------------------------------------------------------------------------
__global__ void __launch_bounds__(256) finalize_kernel(float* __restrict__ out, int nparts,
                                                       double inv_nn) {
    int t = threadIdx.x;
    double s = 0.0;
    for (int i = t; i < nparts; i += 256) s += (double)g_partials[i];
    __shared__ double buf[256];
    buf[t] = s;
    __syncthreads();
    for (int o = 128; o; o >>= 1) {
        if (t < o) buf[t] += buf[t + o];
        __syncthreads();
    }
    if (t == 0) out[0] = (float)(buf[0] * inv_nn);
}

// Pads: ncu captures the 6th global launch (2 harness + norm + 2 pads -> gemm).
__global__ void ncu_pad_kernel() {}

// ---------------------------------------------------------------------------
extern "C" void kernel_launch(void* const* d_in, const int* in_sizes, int n_in,
                              void* d_out, int out_size) {
    const float* emb = (const float*)d_in[0];
    const float* S   = (const float*)d_in[1];
    (void)n_in; (void)out_size;

    long long nn = (long long)in_sizes[1];
    int N = (int)(sqrt((double)nn) + 0.5);
    int T = N / 128;
    int ntiles = T * (T + 1) / 2;

    cudaFuncSetAttribute(gemm_loss_kernel, cudaFuncAttributeMaxDynamicSharedMemorySize,
                         SMEM_BYTES);

    int grid = 148;                      // persistent, 1 CTA/SM (matches measured occ)
    if (grid > ntiles) grid = ntiles;

    normalize_kernel<<<(N + 15) / 16, 512>>>(emb, N);
    ncu_pad_kernel<<<1, 32>>>();
    ncu_pad_kernel<<<1, 32>>>();
    gemm_loss_kernel<<<grid, 512, SMEM_BYTES>>>(S, N, T, ntiles);
    finalize_kernel<<<1, 256>>>((float*)d_out, ntiles, 1.0 / ((double)N * (double)N));
}

// round 12
// speedup vs baseline: 1.0737x; 1.0737x over previous
#include <cuda_runtime.h>
#include <cuda_bf16.h>
#include <cstdint>
#include <cmath>

// loss = mean((normalize(E) @ normalize(E)^T - S)^2), E:[N,128] f32, S:[N,N] f32, N=8192.
//
// v9: exact v3 (best: 83.2us, 2 CTAs/SM) + ONE change: cross-CTA S prefetch.
//  - Each CTA prefetches its OWN S blocks (covers early tiles) AND the S
//    blocks of tile blockIdx+296 (one wave ahead at 2 CTAs/SM x 148 SMs).
//    By the time that CTA launches, its S is L2-resident -> loss phase stops
//    exposing DRAM latency. ~38MB prefetch window << 126MB L2.
//  - Persistence retired (R5/R8 both regressed: occupancy + reg pressure).
//  - Deterministic fixed-order reduction; no float atomics.

#define DK 128
#define MAX_N 8192
#define MAX_T (MAX_N / 128)
#define LDA 136                          // bf16 smem row stride (ldmatrix-safe)

#define SZ_AB (128 * LDA * 2)            // 34816 B per tile
#define SMEM_BYTES (2 * SZ_AB)           // 69632 B -> 2 CTAs/SM

#define WAVE_AHEAD 296                   // 2 CTAs/SM x 148 SMs

__device__ __nv_bfloat16 g_xn[(size_t)MAX_N * DK];
__device__ float g_partials[MAX_T * (MAX_T + 1) / 2];

// ---------------------------------------------------------------------------
__global__ void __launch_bounds__(512) normalize_kernel(const float* __restrict__ emb, int N) {
    int wid = threadIdx.x >> 5, lane = threadIdx.x & 31;
    int row = blockIdx.x * 16 + wid;
    if (row >= N) return;
    float4 v = reinterpret_cast<const float4*>(emb + (size_t)row * DK)[lane];
    float ss = v.x * v.x + v.y * v.y + v.z * v.z + v.w * v.w;
#pragma unroll
    for (int o = 16; o; o >>= 1) ss += __shfl_xor_sync(0xffffffffu, ss, o);
    float inv = 1.0f / fmaxf(sqrtf(ss), 1e-8f);
    __nv_bfloat16* dst = g_xn + (size_t)row * DK + lane * 4;
    dst[0] = __float2bfloat16(v.x * inv);
    dst[1] = __float2bfloat16(v.y * inv);
    dst[2] = __float2bfloat16(v.z * inv);
    dst[3] = __float2bfloat16(v.w * inv);
}

// ---------------------------------------------------------------------------
__device__ __forceinline__ void cp_async16(void* smem_dst, const void* gmem_src) {
    uint32_t d = (uint32_t)__cvta_generic_to_shared(smem_dst);
    asm volatile("cp.async.cg.shared.global [%0], [%1], 16;" :: "r"(d), "l"(gmem_src));
}
__device__ __forceinline__ void l2_prefetch(const void* g) {
    asm volatile("prefetch.global.L2 [%0];" :: "l"(g));
}
__device__ __forceinline__ void ldsm_x4(uint32_t& r0, uint32_t& r1, uint32_t& r2, uint32_t& r3,
                                        const void* p) {
    uint32_t addr = (uint32_t)__cvta_generic_to_shared(p);
    asm volatile("ldmatrix.sync.aligned.m8n8.x4.shared.b16 {%0,%1,%2,%3}, [%4];"
                 : "=r"(r0), "=r"(r1), "=r"(r2), "=r"(r3) : "r"(addr));
}
__device__ __forceinline__ void mma_bf16(float* c, const uint32_t* a, uint32_t b0, uint32_t b1) {
    asm volatile(
        "mma.sync.aligned.m16n8k16.row.col.f32.bf16.bf16.f32 "
        "{%0,%1,%2,%3}, {%4,%5,%6,%7}, {%8,%9}, {%0,%1,%2,%3};"
        : "+f"(c[0]), "+f"(c[1]), "+f"(c[2]), "+f"(c[3])
        : "r"(a[0]), "r"(a[1]), "r"(a[2]), "r"(a[3]), "r"(b0), "r"(b1));
}
__device__ __forceinline__ void decode_tile(int idx, int T, int& bi, int& bj) {
    int b = 0;
    while (idx >= T - b) { idx -= T - b; b++; }
    bi = b; bj = b + idx;
}

// ---------------------------------------------------------------------------
__global__ void __launch_bounds__(512, 2) gemm_loss_kernel(const float* __restrict__ S,
                                                           int N, int T, int ntiles) {
    extern __shared__ char smem[];
    __nv_bfloat16* sA = (__nv_bfloat16*)smem;
    __nv_bfloat16* sB = (__nv_bfloat16*)(smem + SZ_AB);

    int bi, bj;
    decode_tile(blockIdx.x, T, bi, bj);
    const int i0 = bi * 128, j0 = bj * 128;
    const bool offdiag = (bi != bj);

    const int t = threadIdx.x;
    const int w = t >> 5, lane = t & 31;

    // ---- prefetch: own S blocks (early tiles) + one wave ahead ----
    {
        int r = t >> 2, q = (t & 3) * 32;
        l2_prefetch(S + (size_t)(i0 + r) * N + j0 + q);
        if (offdiag) l2_prefetch(S + (size_t)(j0 + r) * N + i0 + q);

        int t2 = blockIdx.x + WAVE_AHEAD;
        if (t2 < ntiles) {
            int bi2, bj2;
            decode_tile(t2, T, bi2, bj2);
            int i2 = bi2 * 128, j2 = bj2 * 128;
            l2_prefetch(S + (size_t)(i2 + r) * N + j2 + q);
            if (bi2 != bj2) l2_prefetch(S + (size_t)(j2 + r) * N + i2 + q);
        }
    }

    // ---- A/B bf16 tiles via cp.async (g_xn is 2MB, L2-hot) ----
#pragma unroll
    for (int it = 0; it < 4; it++) {
        int id = t + it * 512;
        int r = id >> 4, q = id & 15;
        cp_async16(sA + r * LDA + q * 8, g_xn + (size_t)(i0 + r) * DK + q * 8);
        cp_async16(sB + r * LDA + q * 8, g_xn + (size_t)(j0 + r) * DK + q * 8);
    }
    asm volatile("cp.async.commit_group;");
    asm volatile("cp.async.wait_group 0;" ::: "memory");
    __syncthreads();

    // ---- GEMM: 16 warps, each a 32x32 tile ----
    const int wm = w & 3, wn = w >> 2;
    float acc[2][4][4];
#pragma unroll
    for (int mi = 0; mi < 2; mi++)
#pragma unroll
        for (int ni = 0; ni < 4; ni++)
#pragma unroll
            for (int e = 0; e < 4; e++) acc[mi][ni][e] = 0.0f;

    const int a_row_in16 = lane & 15;
    const int a_khalf = (lane >> 4) * 8;
    const int b_row_in16 = (lane & 7) + ((lane >> 4) << 3);
    const int b_khalf = ((lane >> 3) & 1) * 8;

#pragma unroll
    for (int k0 = 0; k0 < DK; k0 += 16) {
        uint32_t a[2][4], b[2][4];
#pragma unroll
        for (int mi = 0; mi < 2; mi++) {
            const __nv_bfloat16* p = sA + (wm * 32 + mi * 16 + a_row_in16) * LDA + (k0 + a_khalf);
            ldsm_x4(a[mi][0], a[mi][1], a[mi][2], a[mi][3], p);
        }
#pragma unroll
        for (int nj = 0; nj < 2; nj++) {
            const __nv_bfloat16* p = sB + (wn * 32 + nj * 16 + b_row_in16) * LDA + (k0 + b_khalf);
            ldsm_x4(b[nj][0], b[nj][1], b[nj][2], b[nj][3], p);
        }
#pragma unroll
        for (int mi = 0; mi < 2; mi++)
#pragma unroll
            for (int ni = 0; ni < 4; ni++) {
                const uint32_t* bp = &b[ni >> 1][(ni & 1) * 2];
                mma_bf16(acc[mi][ni], a[mi], bp[0], bp[1]);
            }
    }

    // ---- loss: registers vs S (L2-resident thanks to wave-ahead prefetch) ----
    const int g = lane >> 2, t4 = lane & 3;
    float lsum = 0.0f;

    // Phase A: vs S[i0+r][j0+c], float2 loads.
#pragma unroll
    for (int mi = 0; mi < 2; mi++)
#pragma unroll
        for (int e2 = 0; e2 < 2; e2++) {
            const float* rowp = S + (size_t)(i0 + wm * 32 + mi * 16 + g + e2 * 8) * N + j0
                                + wn * 32 + t4 * 2;
#pragma unroll
            for (int ni = 0; ni < 4; ni++) {
                float2 s = *reinterpret_cast<const float2*>(rowp + ni * 8);
                float d0 = acc[mi][ni][e2 * 2 + 0] - s.x;
                float d1 = acc[mi][ni][e2 * 2 + 1] - s.y;
                lsum += d0 * d0 + d1 * d1;
            }
        }

    // Phase B: vs S[j0+c][i0+r], scalar loads (coalesced across g).
    if (offdiag) {
#pragma unroll
        for (int ni = 0; ni < 4; ni++)
#pragma unroll
            for (int e1 = 0; e1 < 2; e1++) {
                const float* colp = S + (size_t)(j0 + wn * 32 + ni * 8 + t4 * 2 + e1) * N
                                    + i0 + wm * 32 + g;
#pragma unroll
                for (int mi = 0; mi < 2; mi++)
#pragma unroll
                    for (int e2 = 0; e2 < 2; e2++) {
                        float d = acc[mi][ni][e2 * 2 + e1] - colp[mi * 16 + e2 * 8];
                        lsum += d * d;
                    }
            }
    }

    // ---- deterministic block reduction ----
#pragma unroll
    for (int o = 16; o; o >>= 1) lsum += __shfl_xor_sync(0xffffffffu, lsum, o);
    __shared__ float rbuf[16];
    if (lane == 0) rbuf[w] = lsum;
    __syncthreads();
    if (t == 0) {
        float s = 0.0f;
#pragma unroll
        for (int i = 0; i < 16; i++) s += rbuf[i];
        g_partials[blockIdx.x] = s;
    }
}

// ---------------------------------------------------------------------------
__global__ void __launch_bounds__(256) finalize_kernel(float* __restrict__ out, int nparts,
                                                       double inv_nn) {
    int t = threadIdx.x;
    double s = 0.0;
    for (int i = t; i < nparts; i += 256) s += (double)g_partials[i];
    __shared__ double buf[256];
    buf[t] = s;
    __syncthreads();
    for (int o = 128; o; o >>= 1) {
        if (t < o) buf[t] += buf[t + o];
        __syncthreads();
    }
    if (t == 0) out[0] = (float)(buf[0] * inv_nn);
}

// Pads: ncu captures the 6th global launch (2 harness + norm + 2 pads -> gemm).
__global__ void ncu_pad_kernel() {}

// ---------------------------------------------------------------------------
extern "C" void kernel_launch(void* const* d_in, const int* in_sizes, int n_in,
                              void* d_out, int out_size) {
    const float* emb = (const float*)d_in[0];
    const float* S   = (const float*)d_in[1];
    (void)n_in; (void)out_size;

    long long nn = (long long)in_sizes[1];
    int N = (int)(sqrt((double)nn) + 0.5);
    int T = N / 128;
    int ntiles = T * (T + 1) / 2;

    cudaFuncSetAttribute(gemm_loss_kernel, cudaFuncAttributeMaxDynamicSharedMemorySize,
                         SMEM_BYTES);

    normalize_kernel<<<(N + 15) / 16, 512>>>(emb, N);
    ncu_pad_kernel<<<1, 32>>>();
    ncu_pad_kernel<<<1, 32>>>();
    gemm_loss_kernel<<<ntiles, 512, SMEM_BYTES>>>(S, N, T, ntiles);
    finalize_kernel<<<1, 256>>>((float*)d_out, ntiles, 1.0 / ((double)N * (double)N));
}

// round 16
// speedup vs baseline: 1.0895x; 1.0147x over previous
#include <cuda_runtime.h>
#include <cuda_bf16.h>
#include <cstdint>
#include <cmath>

// loss = mean((normalize(E) @ normalize(E)^T - S)^2), E:[N,128] f32, S:[N,N] f32, N=8192.
//
// v10: v3 (best: 68us kernel) + per-warp transpose epilogue.
//  - L1 wavefronts are the measured wall (6.6K/CTA in v3, ~46us busy).
//    Loss LDGs were sector-fragmented (8 lines/instr). Fix: each warp spills
//    its 32x32 acc into a PRIVATE stride-33 smem block (overlay on dead A/B),
//    then loss reads S with lane on the contiguous axis -> 1 line per LDG.
//    5.1K wf/CTA. Unlike v7: no shared pred buffer, no cross-warp barriers
//    after the spill -> v3's load-level parallelism preserved.
//  - Everything else byte-identical to v3 (2080 CTAs, 2/SM, own-S L2
//    prefetch, register MMA, deterministic reduction).

#define DK 128
#define MAX_N 8192
#define MAX_T (MAX_N / 128)
#define LDA 136                          // bf16 smem row stride (ldmatrix-safe)

#define SZ_AB (128 * LDA * 2)            // 34816 B per tile
#define SMEM_BYTES (2 * SZ_AB)           // 69632 B -> 2 CTAs/SM
#define TR_FLOATS (32 * 33)              // 1056 floats per warp (stride 33)
// overlay: 16 warps * 1056 * 4 = 67584 <= 69632 OK

__device__ __nv_bfloat16 g_xn[(size_t)MAX_N * DK];
__device__ float g_partials[MAX_T * (MAX_T + 1) / 2];

// ---------------------------------------------------------------------------
__global__ void __launch_bounds__(512) normalize_kernel(const float* __restrict__ emb, int N) {
    int wid = threadIdx.x >> 5, lane = threadIdx.x & 31;
    int row = blockIdx.x * 16 + wid;
    if (row >= N) return;
    float4 v = reinterpret_cast<const float4*>(emb + (size_t)row * DK)[lane];
    float ss = v.x * v.x + v.y * v.y + v.z * v.z + v.w * v.w;
#pragma unroll
    for (int o = 16; o; o >>= 1) ss += __shfl_xor_sync(0xffffffffu, ss, o);
    float inv = 1.0f / fmaxf(sqrtf(ss), 1e-8f);
    __nv_bfloat16* dst = g_xn + (size_t)row * DK + lane * 4;
    dst[0] = __float2bfloat16(v.x * inv);
    dst[1] = __float2bfloat16(v.y * inv);
    dst[2] = __float2bfloat16(v.z * inv);
    dst[3] = __float2bfloat16(v.w * inv);
}

// ---------------------------------------------------------------------------
__device__ __forceinline__ void cp_async16(void* smem_dst, const void* gmem_src) {
    uint32_t d = (uint32_t)__cvta_generic_to_shared(smem_dst);
    asm volatile("cp.async.cg.shared.global [%0], [%1], 16;" :: "r"(d), "l"(gmem_src));
}
__device__ __forceinline__ void l2_prefetch(const void* g) {
    asm volatile("prefetch.global.L2 [%0];" :: "l"(g));
}
__device__ __forceinline__ void ldsm_x4(uint32_t& r0, uint32_t& r1, uint32_t& r2, uint32_t& r3,
                                        const void* p) {
    uint32_t addr = (uint32_t)__cvta_generic_to_shared(p);
    asm volatile("ldmatrix.sync.aligned.m8n8.x4.shared.b16 {%0,%1,%2,%3}, [%4];"
                 : "=r"(r0), "=r"(r1), "=r"(r2), "=r"(r3) : "r"(addr));
}
__device__ __forceinline__ void mma_bf16(float* c, const uint32_t* a, uint32_t b0, uint32_t b1) {
    asm volatile(
        "mma.sync.aligned.m16n8k16.row.col.f32.bf16.bf16.f32 "
        "{%0,%1,%2,%3}, {%4,%5,%6,%7}, {%8,%9}, {%0,%1,%2,%3};"
        : "+f"(c[0]), "+f"(c[1]), "+f"(c[2]), "+f"(c[3])
        : "r"(a[0]), "r"(a[1]), "r"(a[2]), "r"(a[3]), "r"(b0), "r"(b1));
}

// ---------------------------------------------------------------------------
__global__ void __launch_bounds__(512, 2) gemm_loss_kernel(const float* __restrict__ S,
                                                           int N, int T) {
    extern __shared__ char smem[];
    __nv_bfloat16* sA = (__nv_bfloat16*)smem;
    __nv_bfloat16* sB = (__nv_bfloat16*)(smem + SZ_AB);

    // blockIdx -> (bi, bj), bi <= bj
    int idx = blockIdx.x, bi = 0;
    while (idx >= T - bi) { idx -= T - bi; bi++; }
    const int bj = bi + idx;
    const int i0 = bi * 128, j0 = bj * 128;
    const bool offdiag = (bi != bj);

    const int t = threadIdx.x;
    const int w = t >> 5, lane = t & 31;

    // ---- L2 prefetch own S blocks: DRAM stream overlaps the MMA ----
    {
        int r = t >> 2, q = (t & 3) * 32;
        l2_prefetch(S + (size_t)(i0 + r) * N + j0 + q);
        if (offdiag) l2_prefetch(S + (size_t)(j0 + r) * N + i0 + q);
    }

    // ---- A/B bf16 tiles via cp.async (g_xn is 2MB, L2-hot) ----
#pragma unroll
    for (int it = 0; it < 4; it++) {
        int id = t + it * 512;
        int r = id >> 4, q = id & 15;
        cp_async16(sA + r * LDA + q * 8, g_xn + (size_t)(i0 + r) * DK + q * 8);
        cp_async16(sB + r * LDA + q * 8, g_xn + (size_t)(j0 + r) * DK + q * 8);
    }
    asm volatile("cp.async.commit_group;");
    asm volatile("cp.async.wait_group 0;" ::: "memory");
    __syncthreads();

    // ---- GEMM: 16 warps, each a 32x32 tile ----
    const int wm = w & 3, wn = w >> 2;
    float acc[2][4][4];
#pragma unroll
    for (int mi = 0; mi < 2; mi++)
#pragma unroll
        for (int ni = 0; ni < 4; ni++)
#pragma unroll
            for (int e = 0; e < 4; e++) acc[mi][ni][e] = 0.0f;

    const int a_row_in16 = lane & 15;
    const int a_khalf = (lane >> 4) * 8;
    const int b_row_in16 = (lane & 7) + ((lane >> 4) << 3);
    const int b_khalf = ((lane >> 3) & 1) * 8;

#pragma unroll
    for (int k0 = 0; k0 < DK; k0 += 16) {
        uint32_t a[2][4], b[2][4];
#pragma unroll
        for (int mi = 0; mi < 2; mi++) {
            const __nv_bfloat16* p = sA + (wm * 32 + mi * 16 + a_row_in16) * LDA + (k0 + a_khalf);
            ldsm_x4(a[mi][0], a[mi][1], a[mi][2], a[mi][3], p);
        }
#pragma unroll
        for (int nj = 0; nj < 2; nj++) {
            const __nv_bfloat16* p = sB + (wn * 32 + nj * 16 + b_row_in16) * LDA + (k0 + b_khalf);
            ldsm_x4(b[nj][0], b[nj][1], b[nj][2], b[nj][3], p);
        }
#pragma unroll
        for (int mi = 0; mi < 2; mi++)
#pragma unroll
            for (int ni = 0; ni < 4; ni++) {
                const uint32_t* bp = &b[ni >> 1][(ni & 1) * 2];
                mma_bf16(acc[mi][ni], a[mi], bp[0], bp[1]);
            }
    }

    // ---- per-warp spill into PRIVATE 32x33 block (overlay; A/B dead) ----
    __syncthreads();                       // all warps done reading sA/sB
    float* tr = (float*)smem + w * TR_FLOATS;
    {
        const int g = lane >> 2, t4 = lane & 3;
#pragma unroll
        for (int mi = 0; mi < 2; mi++)
#pragma unroll
            for (int ni = 0; ni < 4; ni++) {
                int rl = mi * 16 + g, cl = ni * 8 + t4 * 2;
                tr[rl * 33 + cl]           = acc[mi][ni][0];
                tr[rl * 33 + cl + 1]       = acc[mi][ni][1];
                tr[(rl + 8) * 33 + cl]     = acc[mi][ni][2];
                tr[(rl + 8) * 33 + cl + 1] = acc[mi][ni][3];
            }
    }
    __syncwarp();

    // ---- loss: line-perfect LDGs, conflict-free LDS, A/B interleaved ----
    const float* SA = S + (size_t)(i0 + wm * 32) * N + j0 + wn * 32 + lane;
    float lsum = 0.0f;
    if (offdiag) {
        const float* SB = S + (size_t)(j0 + wn * 32) * N + i0 + wm * 32 + lane;
#pragma unroll 4
        for (int rr = 0; rr < 32; rr++) {
            float sa = SA[(size_t)rr * N];          // 1 line per warp-instr
            float sb = SB[(size_t)rr * N];          // 1 line per warp-instr
            float pa = tr[rr * 33 + lane];          // conflict-free
            float pb = tr[lane * 33 + rr];          // conflict-free (stride 33)
            float d0 = pa - sa, d1 = pb - sb;
            lsum += d0 * d0 + d1 * d1;
        }
    } else {
#pragma unroll 4
        for (int rr = 0; rr < 32; rr++) {
            float sa = SA[(size_t)rr * N];
            float pa = tr[rr * 33 + lane];
            float d0 = pa - sa;
            lsum += d0 * d0;
        }
    }

    // ---- deterministic block reduction ----
#pragma unroll
    for (int o = 16; o; o >>= 1) lsum += __shfl_xor_sync(0xffffffffu, lsum, o);
    __shared__ float rbuf[16];
    if (lane == 0) rbuf[w] = lsum;
    __syncthreads();
    if (t == 0) {
        float s = 0.0f;
#pragma unroll
        for (int i = 0; i < 16; i++) s += rbuf[i];
        g_partials[blockIdx.x] = s;
    }
}

// ---------------------------------------------------------------------------
__global__ void __launch_bounds__(256) finalize_kernel(float* __restrict__ out, int nparts,
                                                       double inv_nn) {
    int t = threadIdx.x;
    double s = 0.0;
    for (int i = t; i < nparts; i += 256) s += (double)g_partials[i];
    __shared__ double buf[256];
    buf[t] = s;
    __syncthreads();
    for (int o = 128; o; o >>= 1) {
        if (t < o) buf[t] += buf[t + o];
        __syncthreads();
    }
    if (t == 0) out[0] = (float)(buf[0] * inv_nn);
}

// Pads: ncu captures the 6th global launch (2 harness + norm + 2 pads -> gemm).
__global__ void ncu_pad_kernel() {}

// ---------------------------------------------------------------------------
extern "C" void kernel_launch(void* const* d_in, const int* in_sizes, int n_in,
                              void* d_out, int out_size) {
    const float* emb = (const float*)d_in[0];
    const float* S   = (const float*)d_in[1];
    (void)n_in; (void)out_size;

    long long nn = (long long)in_sizes[1];
    int N = (int)(sqrt((double)nn) + 0.5);
    int T = N / 128;
    int ntiles = T * (T + 1) / 2;

    cudaFuncSetAttribute(gemm_loss_kernel, cudaFuncAttributeMaxDynamicSharedMemorySize,
                         SMEM_BYTES);

    normalize_kernel<<<(N + 15) / 16, 512>>>(emb, N);
    ncu_pad_kernel<<<1, 32>>>();
    ncu_pad_kernel<<<1, 32>>>();
    gemm_loss_kernel<<<ntiles, 512, SMEM_BYTES>>>(S, N, T);
    finalize_kernel<<<1, 256>>>((float*)d_out, ntiles, 1.0 / ((double)N * (double)N));
}